// round 1
// baseline (speedup 1.0000x reference)
#include <cuda_runtime.h>

#define NDIM 1000
#define PDIM 50000
#define ZDIM 10
#define LDIM 5

#define NSPLIT 8
#define NCHUNK (NDIM / NSPLIT)                      // 125
#define K1_THREADS 256
#define K1_PTILE (K1_THREADS * 4)                   // 1024
#define K1_PTILES ((PDIM + K1_PTILE - 1) / K1_PTILE) // 49
#define K1_MAIN (K1_PTILES * NSPLIT)                // 392

#define K2_BLOCKS 98
#define K2_THREADS 256
#define NSTEPS (ZDIM * LDIM)                        // 50

#define OUT_VW_OFF (LDIM * ZDIM * PDIM)             // 250000
#define OUT_AL_OFF (OUT_VW_OFF + LDIM * ZDIM)       // 250050

// Static device scratch (no runtime allocation allowed)
__device__ __align__(16) float g_ztrp[NSPLIT][ZDIM][PDIM];   // 16 MB partials
__device__ float g_mzz[ZDIM * ZDIM];
__device__ __align__(128) float g_part[NSTEPS][128][2];      // per-step per-block (m, s)
__device__ int g_ready[NSTEPS];                              // per-step arrival counters

// ---------------------------------------------------------------------------
// Kernel 1: ZtR partials (ZtR[k,p] = sum_n mean_z[n,k]*data[n,p]) split over
// NSPLIT n-chunks, plus mean_zz, vw output, and barrier-counter reset.
// ---------------------------------------------------------------------------
__global__ __launch_bounds__(K1_THREADS)
void k1_ztr(const float* __restrict__ data,
            const float* __restrict__ mean_z,
            const float* __restrict__ var_z,
            const float* __restrict__ tau_0,
            const float* __restrict__ tau_p,
            float* __restrict__ out_vw)
{
    const int b = blockIdx.x;
    const int tid = threadIdx.x;

    if (b == K1_MAIN) {
        // Aux block: reset counters, compute mean_zz = Z^T Z + N*var_z, write vw.
        if (tid < NSTEPS) g_ready[tid] = 0;
        __shared__ float s_mzz[ZDIM * ZDIM];
        if (tid < ZDIM * ZDIM) {
            int i = tid / ZDIM, j = tid % ZDIM;
            float s = 0.f;
            for (int n = 0; n < NDIM; n++)
                s += mean_z[n * ZDIM + i] * mean_z[n * ZDIM + j];
            s += (float)NDIM * var_z[i * ZDIM + j];
            s_mzz[tid] = s;
            g_mzz[tid] = s;
        }
        __syncthreads();
        if (tid < LDIM * ZDIM) {
            int l = tid / ZDIM, k = tid % ZDIM;
            float tau = tau_p[0];
            out_vw[tid] = 1.0f / (tau * s_mzz[k * ZDIM + k] + tau_0[l * ZDIM + k]);
        }
        return;
    }

    const int pt = b % K1_PTILES;
    const int c  = b / K1_PTILES;

    // mean_z chunk in shared, rows padded to 12 floats for float4 reads.
    __shared__ __align__(16) float s_z[NCHUNK][12];
    for (int i = tid; i < NCHUNK * ZDIM; i += K1_THREADS) {
        int n = i / ZDIM, kk = i % ZDIM;
        s_z[n][kk] = mean_z[(c * NCHUNK + n) * ZDIM + kk];
    }
    __syncthreads();

    const int p0 = pt * K1_PTILE + tid * 4;
    if (p0 >= PDIM) return;   // P divisible by 4 -> p0..p0+3 all valid when p0 < P

    float4 acc[ZDIM];
#pragma unroll
    for (int k = 0; k < ZDIM; k++) acc[k] = make_float4(0.f, 0.f, 0.f, 0.f);

    const float* dptr = data + (size_t)c * NCHUNK * PDIM + p0;
#pragma unroll 2
    for (int n = 0; n < NCHUNK; n++) {
        float4 d = *reinterpret_cast<const float4*>(dptr + (size_t)n * PDIM);
        const float4* zr = reinterpret_cast<const float4*>(s_z[n]);
        float4 z0 = zr[0], z1 = zr[1], z2 = zr[2];
        float zk[ZDIM] = {z0.x, z0.y, z0.z, z0.w, z1.x, z1.y, z1.z, z1.w, z2.x, z2.y};
#pragma unroll
        for (int k = 0; k < ZDIM; k++) {
            acc[k].x = fmaf(zk[k], d.x, acc[k].x);
            acc[k].y = fmaf(zk[k], d.y, acc[k].y);
            acc[k].z = fmaf(zk[k], d.z, acc[k].z);
            acc[k].w = fmaf(zk[k], d.w, acc[k].w);
        }
    }
#pragma unroll
    for (int k = 0; k < ZDIM; k++)
        *reinterpret_cast<float4*>(&g_ztrp[c][k][p0]) = acc[k];
}

// ---------------------------------------------------------------------------
// Kernel 2: persistent serial coordinate-descent sweep. 98 co-resident CTAs,
// each thread owns 2 p-columns (98*256*2 = 50176 >= 50000). One grid-wide
// rendezvous per (k,l) step via per-step counters + per-step partial buffers.
// ---------------------------------------------------------------------------
__global__ __launch_bounds__(K2_THREADS)
void k2_loop(const float* __restrict__ mw_in,
             const float* __restrict__ al_in,
             const float* __restrict__ pi,
             const float* __restrict__ tau_0,
             const float* __restrict__ tau_p,
             float* __restrict__ out)
{
    const int tid  = threadIdx.x;
    const int b    = blockIdx.x;
    const int wid  = tid >> 5;
    const int lane = tid & 31;

    float* out_mw = out;
    float* out_al = out + OUT_AL_OFF;

    __shared__ float s_mzz[ZDIM * ZDIM];
    __shared__ float s_t0[LDIM * ZDIM];
    __shared__ float s_red[8][2];
    __shared__ float s_ms[2];

    if (tid < ZDIM * ZDIM) s_mzz[tid] = g_mzz[tid];
    if (tid < LDIM * ZDIM) s_t0[tid] = tau_0[tid];
    const float tau = tau_p[0];

    const int p0 = b * (K2_THREADS * 2) + tid;     // always < PDIM (max 49919)
    const int p1 = p0 + K2_THREADS;
    const bool v1 = (p1 < PDIM);

    // Per-thread register state: W columns and ZtR columns for its two p's.
    float W[ZDIM][2], Zt[ZDIM][2];
#pragma unroll
    for (int k = 0; k < ZDIM; k++) {
        {
            float zt = 0.f;
#pragma unroll
            for (int c = 0; c < NSPLIT; c++) zt += g_ztrp[c][k][p0];
            float w = 0.f;
#pragma unroll
            for (int l = 0; l < LDIM; l++) {
                size_t idx = (size_t)(l * ZDIM + k) * PDIM + p0;
                w = fmaf(mw_in[idx], al_in[idx], w);
            }
            Zt[k][0] = zt; W[k][0] = w;
        }
        if (v1) {
            float zt = 0.f;
#pragma unroll
            for (int c = 0; c < NSPLIT; c++) zt += g_ztrp[c][k][p1];
            float w = 0.f;
#pragma unroll
            for (int l = 0; l < LDIM; l++) {
                size_t idx = (size_t)(l * ZDIM + k) * PDIM + p1;
                w = fmaf(mw_in[idx], al_in[idx], w);
            }
            Zt[k][1] = zt; W[k][1] = w;
        } else { Zt[k][1] = 0.f; W[k][1] = 0.f; }
    }
    __syncthreads();

#pragma unroll
    for (int k = 0; k < ZDIM; k++) {
        const float Ezz = s_mzz[k * ZDIM + k];
        float Rt[2], Wk[2], lpi[2];
#pragma unroll
        for (int e = 0; e < 2; e++) {
            float s = Zt[k][e];
#pragma unroll
            for (int j = 0; j < ZDIM; j++)
                s -= s_mzz[k * ZDIM + j] * W[j][e];
            Rt[e] = s + Ezz * W[k][e];            // = ZtR[k] - sum_{j!=k} mzz[k,j]*W[j]
            Wk[e] = W[k][e];
        }
        lpi[0] = logf(pi[(size_t)k * PDIM + p0]);
        lpi[1] = v1 ? logf(pi[(size_t)k * PDIM + p1]) : 0.f;

        for (int l = 0; l < LDIM; l++) {
            const int step = k * LDIM + l;
            const float t0    = s_t0[l * ZDIM + k];
            const float u_var = 1.f / (tau * Ezz + t0);
            const float s2    = 1.f / (Ezz * tau);
            const float s0inv = 1.f / t0;
            // logit = log(pi) + C2*r^2  (constant part of log_bf cancels in softmax)
            const float C2 = 0.5f * (tau / Ezz) * (s0inv / (s2 + s0inv));

            float r[2], Wkl[2], lg[2];
            {
                size_t idx = (size_t)(l * ZDIM + k) * PDIM + p0;
                float wm = mw_in[idx], wa = al_in[idx];
                Wkl[0] = Wk[0] - wm * wa;
                r[0]   = Rt[0] - Ezz * Wkl[0];
                lg[0]  = fmaf(C2 * r[0], r[0], lpi[0]);
            }
            if (v1) {
                size_t idx = (size_t)(l * ZDIM + k) * PDIM + p1;
                float wm = mw_in[idx], wa = al_in[idx];
                Wkl[1] = Wk[1] - wm * wa;
                r[1]   = Rt[1] - Ezz * Wkl[1];
                lg[1]  = fmaf(C2 * r[1], r[1], lpi[1]);
            } else { Wkl[1] = 0.f; r[1] = 0.f; lg[1] = -1e30f; }

            // ---- block-level online softmax reduce (m, s) ----
            float m = fmaxf(lg[0], lg[1]);
            float s = expf(lg[0] - m) + expf(lg[1] - m);
#pragma unroll
            for (int o = 16; o > 0; o >>= 1) {
                float mo = __shfl_xor_sync(0xffffffffu, m, o);
                float so = __shfl_xor_sync(0xffffffffu, s, o);
                float nm = fmaxf(m, mo);
                s = s * expf(m - nm) + so * expf(mo - nm);
                m = nm;
            }
            if (lane == 0) { s_red[wid][0] = m; s_red[wid][1] = s; }
            __syncthreads();
            if (wid == 0) {
                float mb = (lane < 8) ? s_red[lane][0] : -1e30f;
                float sb = (lane < 8) ? s_red[lane][1] : 0.f;
#pragma unroll
                for (int o = 4; o > 0; o >>= 1) {
                    float mo = __shfl_xor_sync(0xffffffffu, mb, o);
                    float so = __shfl_xor_sync(0xffffffffu, sb, o);
                    float nm = fmaxf(mb, mo);
                    sb = sb * expf(mb - nm) + so * expf(mo - nm);
                    mb = nm;
                }
                if (lane == 0) {
                    // publish partial, arrive, spin (fresh counter per step)
                    g_part[step][b][0] = mb;
                    g_part[step][b][1] = sb;
                    __threadfence();
                    atomicAdd(&g_ready[step], 1);
                    volatile int* rp = &g_ready[step];
                    while (*rp < K2_BLOCKS) { }
                }
            }
            __syncthreads();

            // ---- grid-level combine (warp 0), L1-bypassed reads ----
            if (wid == 0) {
                __threadfence();
                float gm = -1e30f, gs = 0.f;
                for (int i = lane; i < K2_BLOCKS; i += 32) {
                    float mb = __ldcg(&g_part[step][i][0]);
                    float sb = __ldcg(&g_part[step][i][1]);
                    float nm = fmaxf(gm, mb);
                    gs = gs * expf(gm - nm) + sb * expf(mb - nm);
                    gm = nm;
                }
#pragma unroll
                for (int o = 16; o > 0; o >>= 1) {
                    float mo = __shfl_xor_sync(0xffffffffu, gm, o);
                    float so = __shfl_xor_sync(0xffffffffu, gs, o);
                    float nm = fmaxf(gm, mo);
                    gs = gs * expf(gm - nm) + so * expf(mo - nm);
                    gm = nm;
                }
                if (lane == 0) { s_ms[0] = gm; s_ms[1] = gs; }
            }
            __syncthreads();
            const float gm = s_ms[0];
            const float gs = s_ms[1];

            // ---- normalize, update Wk, store outputs ----
            {
                float a  = expf(lg[0] - gm) / gs;
                float um = tau * u_var * r[0];
                Wk[0] = Wkl[0] + um * a;
                size_t idx = (size_t)(l * ZDIM + k) * PDIM + p0;
                out_mw[idx] = um;
                out_al[idx] = a;
            }
            if (v1) {
                float a  = expf(lg[1] - gm) / gs;
                float um = tau * u_var * r[1];
                Wk[1] = Wkl[1] + um * a;
                size_t idx = (size_t)(l * ZDIM + k) * PDIM + p1;
                out_mw[idx] = um;
                out_al[idx] = a;
            }
        }
        W[k][0] = Wk[0];
        W[k][1] = Wk[1];
    }
}

// ---------------------------------------------------------------------------
extern "C" void kernel_launch(void* const* d_in, const int* in_sizes, int n_in,
                              void* d_out, int out_size)
{
    (void)in_sizes; (void)n_in; (void)out_size;
    const float* data   = (const float*)d_in[0];
    const float* mean_z = (const float*)d_in[1];
    const float* var_z  = (const float*)d_in[2];
    const float* mean_w = (const float*)d_in[3];
    // d_in[4] = var_w (unused: vw output fully overwritten)
    const float* alpha  = (const float*)d_in[5];
    const float* tau_0  = (const float*)d_in[6];
    const float* pi     = (const float*)d_in[7];
    const float* tau    = (const float*)d_in[8];
    float* out = (float*)d_out;

    k1_ztr<<<K1_MAIN + 1, K1_THREADS>>>(data, mean_z, var_z, tau_0, tau,
                                        out + OUT_VW_OFF);
    k2_loop<<<K2_BLOCKS, K2_THREADS>>>(mean_w, alpha, pi, tau_0, tau, out);
}